// round 2
// baseline (speedup 1.0000x reference)
#include <cuda_runtime.h>
#include <cuda_bf16.h>

// ---------------------------------------------------------------------------
// EventTokenizer: T=262144 frames, D_IN=512, K=64 contiguous segments.
// Dominated by one 512MB streaming reduction (features -> per-segment sums).
// ---------------------------------------------------------------------------

#define TFRAMES   262144
#define KSEG      64
#define DIN       512
#define DMODEL    256
#define TYPEEMB   32
#define ZDIM      552      // 512 + 8 + 32
#define EPSF      1e-6f
#define CONF_TH   0.3f

// Output layout (float32, concatenated in reference return order):
// tokens [64*256] | mask [64] | type [64] | conf [64] | s_k [64*8]
#define OUT_TOKENS 0
#define OUT_MASK   16384
#define OUT_TYPE   16448
#define OUT_CONF   16512
#define OUT_SK     16576

// ----- scratch (device globals; no allocation allowed) -----
__device__ float g_esum[KSEG * DIN];   // per-segment feature sums
__device__ float g_sumE[KSEG];
__device__ int   g_maxE[KSEG];         // float bits (energy >= 0)
__device__ float g_sumFC[KSEG];
__device__ float g_sumSC[KSEG * 3];
__device__ float g_sk[KSEG * 8];

// ---------------------------------------------------------------------------
__global__ void k_zero() {
    int i = blockIdx.x * blockDim.x + threadIdx.x;
    if (i < KSEG * DIN) g_esum[i] = 0.f;
    if (i < KSEG) { g_sumE[i] = 0.f; g_maxE[i] = 0; g_sumFC[i] = 0.f; }
    if (i < KSEG * 3) g_sumSC[i] = 0.f;
}

// ---------------------------------------------------------------------------
// Big pass: 512MB of features. 1024 blocks x 256 frames/chunk.
// 128 threads: thread t owns float4 columns [4t, 4t+4). Register accumulate,
// flush by atomicAdd only on segment boundary / chunk end.
__global__ void __launch_bounds__(128) k_feat(const float4* __restrict__ feat,
                                              const int* __restrict__ segend) {
    __shared__ int send[KSEG];
    if (threadIdx.x < KSEG) send[threadIdx.x] = segend[threadIdx.x];
    __syncthreads();

    const int tid = threadIdx.x;
    int f        = blockIdx.x * 256;
    const int f1 = f + 256;

    int cur = 0;
    while (send[cur] <= f) cur++;

    float4 acc = make_float4(0.f, 0.f, 0.f, 0.f);
    const float4* p = feat + (size_t)f * 128 + tid;

    #pragma unroll 4
    for (; f < f1; ++f, p += 128) {
        if (f >= send[cur]) {                       // rare: segment boundary
            float* dst = &g_esum[cur * DIN + tid * 4];
            atomicAdd(dst + 0, acc.x); atomicAdd(dst + 1, acc.y);
            atomicAdd(dst + 2, acc.z); atomicAdd(dst + 3, acc.w);
            acc = make_float4(0.f, 0.f, 0.f, 0.f);
            while (send[cur] <= f) cur++;
        }
        float4 v = *p;
        acc.x += v.x; acc.y += v.y; acc.z += v.z; acc.w += v.w;
    }
    float* dst = &g_esum[cur * DIN + tid * 4];
    atomicAdd(dst + 0, acc.x); atomicAdd(dst + 1, acc.y);
    atomicAdd(dst + 2, acc.z); atomicAdd(dst + 3, acc.w);
}

// ---------------------------------------------------------------------------
// Scalar per-frame reductions: sum/max energy, sum frame_conf, sum stream_conf.
// 64 blocks x 256 threads x 16 contiguous frames/thread.
__global__ void __launch_bounds__(256) k_scal(const float* __restrict__ energy,
                                              const float* __restrict__ fconf,
                                              const float* __restrict__ sconf,
                                              const int* __restrict__ segend) {
    __shared__ int send[KSEG];
    if (threadIdx.x < KSEG) send[threadIdx.x] = segend[threadIdx.x];
    __syncthreads();

    int base = blockIdx.x * 4096 + threadIdx.x * 16;
    int cur = 0;
    while (send[cur] <= base) cur++;

    float sE = 0.f, mx = 0.f, aF = 0.f, s0 = 0.f, s1 = 0.f, s2 = 0.f;
    #pragma unroll
    for (int i = 0; i < 16; ++i) {
        int f = base + i;
        if (f >= send[cur]) {
            atomicAdd(&g_sumE[cur], sE);
            atomicMax(&g_maxE[cur], __float_as_int(mx));
            atomicAdd(&g_sumFC[cur], aF);
            atomicAdd(&g_sumSC[cur * 3 + 0], s0);
            atomicAdd(&g_sumSC[cur * 3 + 1], s1);
            atomicAdd(&g_sumSC[cur * 3 + 2], s2);
            sE = mx = aF = s0 = s1 = s2 = 0.f;
            while (send[cur] <= f) cur++;
        }
        float e = energy[f];
        sE += e; mx = fmaxf(mx, e);
        aF += fconf[f];
        s0 += sconf[3 * f + 0]; s1 += sconf[3 * f + 1]; s2 += sconf[3 * f + 2];
    }
    atomicAdd(&g_sumE[cur], sE);
    atomicMax(&g_maxE[cur], __float_as_int(mx));
    atomicAdd(&g_sumFC[cur], aF);
    atomicAdd(&g_sumSC[cur * 3 + 0], s0);
    atomicAdd(&g_sumSC[cur * 3 + 1], s1);
    atomicAdd(&g_sumSC[cur * 3 + 2], s2);
}

// ---------------------------------------------------------------------------
// Per-segment pass 2: entropy (needs sum_e), s_k, conf, mask, type epilogue.
__global__ void __launch_bounds__(256) k_seg(const float* __restrict__ energy,
                                             const int* __restrict__ segstart,
                                             const int* __restrict__ segend,
                                             const int* __restrict__ etype,
                                             const int* __restrict__ fpsp,
                                             float* __restrict__ out) {
    const int k = blockIdx.x;
    const int s = segstart[k];
    const int e = segend[k];
    const float sumE = g_sumE[k];
    const float inv_den = 1.f / (sumE + EPSF);

    float local = 0.f;
    for (int f = s + threadIdx.x; f < e; f += 256) {
        float p = energy[f] * inv_den;
        local += p * __logf(p + EPSF);
    }
    // block reduce
    #pragma unroll
    for (int o = 16; o; o >>= 1) local += __shfl_xor_sync(~0u, local, o);
    __shared__ float red[8];
    if ((threadIdx.x & 31) == 0) red[threadIdx.x >> 5] = local;
    __syncthreads();

    if (threadIdx.x == 0) {
        float tot = 0.f;
        #pragma unroll
        for (int w = 0; w < 8; ++w) tot += red[w];
        const float ent = -tot;

        const float len = (float)(e - s);
        const float inv = 1.f / len;

        // fps may arrive as int32 or float32: sniff the bit pattern.
        int iv = fpsp[0];
        float fps = (iv >= 1 && iv <= 1000000) ? (float)iv : __int_as_float(iv);

        float sk[8];
        sk[0] = log1pf(len / fps);                         // duration_sec
        sk[1] = log1pf((float)s / fps);                    // latency_sec
        sk[2] = log1pf(sumE * inv);                        // mean_motion
        sk[3] = log1pf(__int_as_float(g_maxE[k]));         // peak_motion
        sk[4] = log1pf(ent);                               // motion_entropy
        sk[5] = log1pf(g_sumSC[k * 3 + 0] * inv);          // vis0
        sk[6] = log1pf(g_sumSC[k * 3 + 1] * inv);          // vis1
        sk[7] = log1pf(g_sumSC[k * 3 + 2] * inv);          // vis2

        float conf = g_sumFC[k] * inv;

        #pragma unroll
        for (int i = 0; i < 8; ++i) {
            g_sk[k * 8 + i] = sk[i];
            out[OUT_SK + k * 8 + i] = sk[i];
        }
        out[OUT_MASK + k] = (conf >= CONF_TH) ? 1.f : 0.f;
        out[OUT_TYPE + k] = (float)etype[k];
        out[OUT_CONF + k] = conf;
    }
}

// ---------------------------------------------------------------------------
// tokens[k][m] = sum_j z[k][j] * W[m][j] + bias[m]; z = [mean_feat | s_k | emb]
// grid (64 segs, 4 m-tiles of 64), 256 thr = 8 warps, warp computes 8 outputs
// with coalesced W row reads + shfl reduce. W (565KB) stays L2-resident.
__global__ void __launch_bounds__(256) k_gemm(const float* __restrict__ W,
                                              const float* __restrict__ bias,
                                              const float* __restrict__ emb,
                                              const int* __restrict__ etype,
                                              const int* __restrict__ segstart,
                                              const int* __restrict__ segend,
                                              float* __restrict__ out) {
    __shared__ float z[ZDIM];
    const int k = blockIdx.x;
    const float inv = 1.f / (float)(segend[k] - segstart[k]);
    const int ty = etype[k];

    for (int i = threadIdx.x; i < ZDIM; i += 256) {
        float v;
        if (i < DIN)            v = g_esum[k * DIN + i] * inv;
        else if (i < DIN + 8)   v = g_sk[k * 8 + (i - DIN)];
        else                    v = emb[ty * TYPEEMB + (i - DIN - 8)];
        z[i] = v;
    }
    __syncthreads();

    const int w    = threadIdx.x >> 5;
    const int lane = threadIdx.x & 31;
    const int mbase = blockIdx.y * 64 + w * 8;

    #pragma unroll
    for (int r = 0; r < 8; ++r) {
        const int m = mbase + r;
        const float* Wr = W + (size_t)m * ZDIM;
        float acc = 0.f;
        for (int j = lane; j < ZDIM; j += 32) acc += z[j] * Wr[j];
        #pragma unroll
        for (int o = 16; o; o >>= 1) acc += __shfl_xor_sync(~0u, acc, o);
        if (lane == 0) out[OUT_TOKENS + k * DMODEL + m] = acc + bias[m];
    }
}

// ---------------------------------------------------------------------------
extern "C" void kernel_launch(void* const* d_in, const int* in_sizes, int n_in,
                              void* d_out, int out_size) {
    const float* features  = (const float*)d_in[0];   // [T, 512]
    const float* energy    = (const float*)d_in[1];   // [T]
    const float* fconf     = (const float*)d_in[2];   // [T]
    const float* sconf     = (const float*)d_in[3];   // [T, 3]
    const int*   seg_start = (const int*)  d_in[4];   // [64]
    const int*   seg_end   = (const int*)  d_in[5];   // [64]
    const int*   etype     = (const int*)  d_in[6];   // [64]
    const float* emb       = (const float*)d_in[7];   // [16, 32]
    const float* W         = (const float*)d_in[8];   // [256, 552]
    const float* bias      = (const float*)d_in[9];   // [256]
    const int*   fps       = (const int*)  d_in[10];  // scalar
    float* out = (float*)d_out;

    k_zero<<<128, 256>>>();
    k_feat<<<1024, 128>>>((const float4*)features, seg_end);
    k_scal<<<64, 256>>>(energy, fconf, sconf, seg_end);
    k_seg <<<64, 256>>>(energy, seg_start, seg_end, etype, fps, out);
    k_gemm<<<dim3(64, 4), 256>>>(W, bias, emb, etype, seg_start, seg_end, out);
}